// round 3
// baseline (speedup 1.0000x reference)
#include <cuda_runtime.h>
#include <stdint.h>

// Polar encoder, N=1024, K=512. One warp per row, bit-packed.
// Mapping: position p = j*128 + lane*4 + b  <->  lane holds reg bit (4j+b).
// Stages on position bits {0,1,7,8,9} are in-register shift/mask XOR;
// bits {2..6} are lane bits -> shfl_xor. Fast path (info bits = tail 512):
// 4x LDG.128 pack, no ballots/shfl/smem. Float4 stores from own register.

#define PN 1024
#define PK 512
#define WARPS_PER_CTA 8
#define CTA_THREADS (32 * WARPS_PER_CTA)

__global__ __launch_bounds__(CTA_THREADS)
void polar_encode_kernel(const float* __restrict__ u,
                         const int*   __restrict__ info_pos,
                         float* __restrict__ out,
                         int batch, int kcount) {
    const int tid  = threadIdx.x;
    const int lane = tid & 31;
    const int warp = tid >> 5;
    const int row  = blockIdx.x * WARPS_PER_CTA + warp;

    __shared__ int s_fast;
    __shared__ int s_inv[PN];                         // general path only
    __shared__ unsigned s_ubits[WARPS_PER_CTA][17];   // general path only

    // ---- per-CTA fast-layout check: kcount==512 && info_pos[k]==512+k ----
    if (tid == 0) s_fast = (kcount == PK) ? 1 : 0;
    __syncthreads();
    const int frozen = PN - kcount;
    for (int k = tid; k < kcount; k += CTA_THREADS) {
        if (info_pos[k] != frozen + k) s_fast = 0;    // benign race, all write 0
    }
    __syncthreads();
    const int fast = s_fast;

    if (!fast) {
        for (int i = tid; i < PN; i += CTA_THREADS) s_inv[i] = -1;
        __syncthreads();
        for (int k = tid; k < kcount; k += CTA_THREADS) s_inv[info_pos[k]] = k;
        __syncthreads();
    }

    if (row >= batch) return;

    unsigned x = 0u;

    if (fast) {
        // info index k = i*128 + 4*lane + b  ->  p = 512 + k
        // -> j = 4+i, reg bit = 4*(4+i) + b = 16 + 4i + b
        const float4* up4 = (const float4*)(u + (size_t)row * PK);
        float4 v0 = up4[0 * 32 + lane];
        float4 v1 = up4[1 * 32 + lane];
        float4 v2 = up4[2 * 32 + lane];
        float4 v3 = up4[3 * 32 + lane];
        unsigned n0 = (v0.x != 0.0f) | ((v0.y != 0.0f) << 1) |
                      ((v0.z != 0.0f) << 2) | ((v0.w != 0.0f) << 3);
        unsigned n1 = (v1.x != 0.0f) | ((v1.y != 0.0f) << 1) |
                      ((v1.z != 0.0f) << 2) | ((v1.w != 0.0f) << 3);
        unsigned n2 = (v2.x != 0.0f) | ((v2.y != 0.0f) << 1) |
                      ((v2.z != 0.0f) << 2) | ((v2.w != 0.0f) << 3);
        unsigned n3 = (v3.x != 0.0f) | ((v3.y != 0.0f) << 1) |
                      ((v3.z != 0.0f) << 2) | ((v3.w != 0.0f) << 3);
        x = (n0 << 16) | (n1 << 20) | (n2 << 24) | (n3 << 28);
    } else {
        // pack u into smem words (word m bit l = u[32m+l] != 0)
        const float* up = u + (size_t)row * PK;
        const int nwords = (kcount + 31) >> 5;
        for (int j = 0; j < nwords; j++) {
            int idx = j * 32 + lane;
            float v = (idx < kcount) ? up[idx] : 0.0f;
            unsigned b = __ballot_sync(0xffffffffu, v != 0.0f);
            if (lane == j) s_ubits[warp][j & 15] = b;  // nwords<=16
        }
        __syncwarp();
        // gather this lane's 32 bits: reg bit r=4j+b <- position j*128+4*lane+b
#pragma unroll 4
        for (int r = 0; r < 32; r++) {
            int j = r >> 2, b = r & 3;
            int p = j * 128 + lane * 4 + b;
            int k = s_inv[p];
            if (k >= 0)
                x |= ((s_ubits[warp][k >> 5] >> (k & 31)) & 1u) << r;
        }
    }

    // ---- butterfly: in-register stages (position bits 0,1,7,8,9) ----
    x ^= (x >> 1)  & 0x55555555u;   // s=0 (b bit 0)
    x ^= (x >> 2)  & 0x33333333u;   // s=1 (b bit 1)
    x ^= (x >> 4)  & 0x0f0f0f0fu;   // s=7 (j bit 0)
    x ^= (x >> 8)  & 0x00ff00ffu;   // s=8 (j bit 1)
    x ^= (x >> 16) & 0x0000ffffu;   // s=9 (j bit 2)

    // ---- cross-lane stages (position bits 2..6 = lane bits 0..4) ----
#pragma unroll
    for (int d = 1; d <= 16; d <<= 1) {
        unsigned y = __shfl_xor_sync(0xffffffffu, x, d);
        if ((lane & d) == 0) x ^= y;
    }

    // ---- unpack: lane's reg bits 4j..4j+3 -> float4 at p = j*128+4*lane ----
    float4* op = (float4*)(out + (size_t)row * PN);
#pragma unroll
    for (int j = 0; j < 8; j++) {
        unsigned nib = x >> (4 * j);
        float4 f;
        f.x = __uint_as_float((nib & 1u)        * 0x3f800000u);
        f.y = __uint_as_float(((nib >> 1) & 1u) * 0x3f800000u);
        f.z = __uint_as_float(((nib >> 2) & 1u) * 0x3f800000u);
        f.w = __uint_as_float(((nib >> 3) & 1u) * 0x3f800000u);
        op[j * 32 + lane] = f;
    }
}

extern "C" void kernel_launch(void* const* d_in, const int* in_sizes, int n_in,
                              void* d_out, int out_size) {
    const float* u        = (const float*)d_in[0];
    const int*   info_pos = (const int*)d_in[1];
    // d_in[2] = ind_gather: butterfly structure fixed by N; unused.

    const int kcount = in_sizes[1];              // 512
    const int batch  = in_sizes[0] / kcount;     // 65536
    float* out = (float*)d_out;

    int ctas = (batch + WARPS_PER_CTA - 1) / WARPS_PER_CTA;
    polar_encode_kernel<<<ctas, CTA_THREADS>>>(u, info_pos, out, batch, kcount);
}